// round 2
// baseline (speedup 1.0000x reference)
#include <cuda_runtime.h>

// ----------------------------------------------------------------------------
// Associative3DEmbedding: two-tower MLP (2048->256->128->64) on feat1/feat2,
// row-normalize, all-pairs cosine -> sigmoid(5*cos).
//
// Round 2: same full-FP32 baseline as R1 (R1 never ran: broker infra failure),
// hardened: positional-fallback input resolution, static smem in k2.
//   k1: H1 = relu(X @ W1 + b1)            X = [feat1; feat2]  (16384 x 2048)
//   k2: E  = relu(H1@W2+b2) @ W3 + b3 ; N = E / max(||E||, 1e-8)
//   k3: out = sigmoid(5 * N1 @ N2^T)      (8192 x 8192)
// Scratch lives in __device__ globals (no allocation).
// ----------------------------------------------------------------------------

#define NZ    2048
#define D1    256
#define D2    128
#define D3    64
#define NHALF 8192
#define NROWS 16384

__device__ float g_h1[(size_t)NROWS * D1];  // 16 MB
__device__ float g_n [(size_t)NROWS * D3];  //  4 MB

// ============================================================================
// k1: SGEMM  H1[16384,256] = relu(X @ W1 + b1)
// Tiles: BM=128, BN=64, BK=16. 256 threads (16x16), microtile 8x4.
// Double-buffered smem, register-prefetched global loads.
// ============================================================================
__global__ __launch_bounds__(256) void k1_gemm_relu(
    const float* __restrict__ f1, const float* __restrict__ f2,
    const float* __restrict__ W1, const float* __restrict__ b1)
{
    __shared__ float As[2][16][132];  // [k][m], padded (+4) for bank spread
    __shared__ float Bs[2][16][64];   // [k][n]

    const int tid = threadIdx.x;
    const int tx  = tid & 15;         // 0..15 -> n
    const int ty  = tid >> 4;         // 0..15 -> m
    const int row0 = blockIdx.x * 128;
    const int col0 = blockIdx.y * 64;

    const float* X = (row0 < NHALF) ? (f1 + (size_t)row0 * NZ)
                                    : (f2 + (size_t)(row0 - NHALF) * NZ);

    // A-tile load map: 512 float4 (128 rows x 4 f4); 2 per thread.
    const int arow = tid >> 2;        // 0..63  (and arow+64)
    const int ak4  = (tid & 3) * 4;   // k offset within tile
    // B-tile load map: 256 float4 (16 rows x 16 f4); 1 per thread.
    const int brow = tid >> 4;        // 0..15 (k within tile)
    const int bn4  = (tid & 15) * 4;  // n offset

    // prefetch tile 0
    float4 ra0 = *(const float4*)(X + (size_t)arow        * NZ + ak4);
    float4 ra1 = *(const float4*)(X + (size_t)(arow + 64) * NZ + ak4);
    float4 rb  = *(const float4*)(W1 + (size_t)brow * D1 + col0 + bn4);

    As[0][ak4 + 0][arow] = ra0.x; As[0][ak4 + 1][arow] = ra0.y;
    As[0][ak4 + 2][arow] = ra0.z; As[0][ak4 + 3][arow] = ra0.w;
    As[0][ak4 + 0][arow + 64] = ra1.x; As[0][ak4 + 1][arow + 64] = ra1.y;
    As[0][ak4 + 2][arow + 64] = ra1.z; As[0][ak4 + 3][arow + 64] = ra1.w;
    *(float4*)&Bs[0][brow][bn4] = rb;
    __syncthreads();

    float acc[8][4];
#pragma unroll
    for (int i = 0; i < 8; i++)
#pragma unroll
        for (int j = 0; j < 4; j++) acc[i][j] = 0.0f;

    int buf = 0;
    const int NT = NZ / 16;  // 128 k-tiles
    for (int kt = 1; kt <= NT; kt++) {
        if (kt < NT) {
            const int kb = kt * 16;
            ra0 = *(const float4*)(X + (size_t)arow        * NZ + kb + ak4);
            ra1 = *(const float4*)(X + (size_t)(arow + 64) * NZ + kb + ak4);
            rb  = *(const float4*)(W1 + (size_t)(kb + brow) * D1 + col0 + bn4);
        }
#pragma unroll
        for (int k = 0; k < 16; k++) {
            float4 a0 = *(const float4*)&As[buf][k][ty * 8];
            float4 a1 = *(const float4*)&As[buf][k][ty * 8 + 4];
            float4 b  = *(const float4*)&Bs[buf][k][tx * 4];
            float av[8] = {a0.x, a0.y, a0.z, a0.w, a1.x, a1.y, a1.z, a1.w};
            float bv[4] = {b.x, b.y, b.z, b.w};
#pragma unroll
            for (int i = 0; i < 8; i++)
#pragma unroll
                for (int j = 0; j < 4; j++) acc[i][j] += av[i] * bv[j];
        }
        if (kt < NT) {
            const int nb = buf ^ 1;
            As[nb][ak4 + 0][arow] = ra0.x; As[nb][ak4 + 1][arow] = ra0.y;
            As[nb][ak4 + 2][arow] = ra0.z; As[nb][ak4 + 3][arow] = ra0.w;
            As[nb][ak4 + 0][arow + 64] = ra1.x; As[nb][ak4 + 1][arow + 64] = ra1.y;
            As[nb][ak4 + 2][arow + 64] = ra1.z; As[nb][ak4 + 3][arow + 64] = ra1.w;
            *(float4*)&Bs[nb][brow][bn4] = rb;
        }
        __syncthreads();
        buf ^= 1;
    }

    // epilogue: +bias, relu, store
    const float4 bv = *(const float4*)(b1 + col0 + tx * 4);
#pragma unroll
    for (int i = 0; i < 8; i++) {
        const size_t r = (size_t)(row0 + ty * 8 + i);
        float4 o;
        o.x = fmaxf(acc[i][0] + bv.x, 0.0f);
        o.y = fmaxf(acc[i][1] + bv.y, 0.0f);
        o.z = fmaxf(acc[i][2] + bv.z, 0.0f);
        o.w = fmaxf(acc[i][3] + bv.w, 0.0f);
        *(float4*)&g_h1[r * D1 + col0 + tx * 4] = o;
    }
}

// ============================================================================
// k2: fused  H2 = relu(H1@W2+b2); E = H2@W3+b3; N = E / max(||E||,1e-8)
// 32 rows per block, 256 threads. Static smem: H1 tile (32x256) + H2 tile
// (32x128) = 49152 B. E reuses the H1 region; inv-norms reuse H2 region.
// W2/W3 read via coalesced LDG (L2-resident, broadcast across block rows).
// ============================================================================
__global__ __launch_bounds__(256) void k2_fused_tail(
    const float* __restrict__ W2, const float* __restrict__ b2,
    const float* __restrict__ W3, const float* __restrict__ b3)
{
    __shared__ float sm[32 * 256 + 32 * 128];
    float* sH1 = sm;                 // 32*256
    float* sH2 = sm + 32 * 256;      // 32*128
    float* sE  = sm;                 // aliases sH1 (valid after layer2)
    float* sNrm = sm + 32 * 256;     // aliases sH2 (valid after layer3)

    const int tid = threadIdx.x;
    const int r0  = blockIdx.x * 32;
    const float* src = g_h1 + (size_t)r0 * D1;

    // load 32x256 H1 tile (linear copy, 8 float4 per thread)
#pragma unroll
    for (int j = 0; j < 8; j++) {
        const int idx = tid + j * 256;          // f4 index, 2048 total
        *(float4*)&sH1[idx * 4] = *(const float4*)(src + (size_t)idx * 4);
    }
    __syncthreads();

    // ---- layer 2: h2[r][jc] = relu(sum_k h1[r][k]*W2[k][jc] + b2[jc]) ----
    {
        const int jc = tid & 127;     // output col
        const int rh = tid >> 7;      // row half: rows rh*16 .. rh*16+15
        float acc[16];
#pragma unroll
        for (int r = 0; r < 16; r++) acc[r] = 0.0f;
        for (int k = 0; k < D1; k += 4) {
            const float w0 = W2[(size_t)(k + 0) * D2 + jc];
            const float w1 = W2[(size_t)(k + 1) * D2 + jc];
            const float w2 = W2[(size_t)(k + 2) * D2 + jc];
            const float w3 = W2[(size_t)(k + 3) * D2 + jc];
#pragma unroll
            for (int r = 0; r < 16; r++) {
                const float4 h = *(const float4*)&sH1[(rh * 16 + r) * D1 + k];
                acc[r] += h.x * w0 + h.y * w1 + h.z * w2 + h.w * w3;
            }
        }
        const float bb = b2[jc];
#pragma unroll
        for (int r = 0; r < 16; r++)
            sH2[(rh * 16 + r) * D2 + jc] = fmaxf(acc[r] + bb, 0.0f);
    }
    __syncthreads();

    // ---- layer 3: e[r][c] = sum_k h2[r][k]*W3[k][c] + b3[c] ----
    {
        const int c  = tid & 63;
        const int rg = tid >> 6;      // 0..3 -> rows rg*8 .. rg*8+7
        float acc[8];
#pragma unroll
        for (int r = 0; r < 8; r++) acc[r] = 0.0f;
        for (int k = 0; k < D2; k += 4) {
            const float w0 = W3[(size_t)(k + 0) * D3 + c];
            const float w1 = W3[(size_t)(k + 1) * D3 + c];
            const float w2 = W3[(size_t)(k + 2) * D3 + c];
            const float w3 = W3[(size_t)(k + 3) * D3 + c];
#pragma unroll
            for (int r = 0; r < 8; r++) {
                const float4 h = *(const float4*)&sH2[(rg * 8 + r) * D2 + k];
                acc[r] += h.x * w0 + h.y * w1 + h.z * w2 + h.w * w3;
            }
        }
        const float bb = b3[c];
#pragma unroll
        for (int r = 0; r < 8; r++)
            sE[(rg * 8 + r) * D3 + c] = acc[r] + bb;
    }
    __syncthreads();

    // ---- inverse norms (warp 0; one lane per row) ----
    if (tid < 32) {
        float ss = 0.0f;
#pragma unroll
        for (int c = 0; c < D3; c += 4) {
            const float4 e = *(const float4*)&sE[tid * D3 + c];
            ss += e.x * e.x + e.y * e.y + e.z * e.z + e.w * e.w;
        }
        const float nrm = sqrtf(ss);
        sNrm[tid] = 1.0f / fmaxf(nrm, 1e-8f);
    }
    __syncthreads();

    // ---- normalize + store (2 float4 per thread) ----
    float* dst = g_n + (size_t)r0 * D3;
#pragma unroll
    for (int j = 0; j < 2; j++) {
        const int idx = tid + j * 256;          // f4 index, 512 total
        const int r   = idx >> 4;               // 16 f4 per row
        const int c4  = (idx & 15) * 4;
        const float inv = sNrm[r];
        float4 e = *(const float4*)&sE[r * D3 + c4];
        e.x *= inv; e.y *= inv; e.z *= inv; e.w *= inv;
        *(float4*)(dst + (size_t)r * D3 + c4) = e;
    }
}

// ============================================================================
// k3: out[8192,8192] = sigmoid(5 * N1 @ N2^T), K=64.
// 128x128 tile, 256 threads (16x16), 8x8 microtile (cols split 4+4 for
// coalesced stores). K processed in two 32-wide smem chunks (<48KB static).
// ============================================================================
__global__ __launch_bounds__(256) void k3_cos_sigmoid(float* __restrict__ out)
{
    __shared__ float As[128][32];    // [m][k]  (direct stores; broadcasty reads)
    __shared__ float Bs[32][132];    // [k][n]  transposed, padded

    const int tid = threadIdx.x;
    const int tx  = tid & 15;
    const int ty  = tid >> 4;
    const int n0  = blockIdx.x * 128;
    const int m0  = blockIdx.y * 128;

    const float* Am = g_n + (size_t)m0 * D3;
    const float* Bm = g_n + (size_t)(NHALF + n0) * D3;

    float acc[8][8];
#pragma unroll
    for (int i = 0; i < 8; i++)
#pragma unroll
        for (int j = 0; j < 8; j++) acc[i][j] = 0.0f;

    for (int kb = 0; kb < 2; kb++) {
        const int kbase = kb * 32;
        // 1024 float4 per tile side; 4 per thread
#pragma unroll
        for (int j = 0; j < 4; j++) {
            const int idx = tid + j * 256;
            const int r   = idx >> 3;            // 0..127
            const int c4  = (idx & 7) * 4;       // 0..28
            const float4 v = *(const float4*)(Am + (size_t)r * D3 + kbase + c4);
            *(float4*)&As[r][c4] = v;
            const float4 w = *(const float4*)(Bm + (size_t)r * D3 + kbase + c4);
            Bs[c4 + 0][r] = w.x; Bs[c4 + 1][r] = w.y;
            Bs[c4 + 2][r] = w.z; Bs[c4 + 3][r] = w.w;
        }
        __syncthreads();

#pragma unroll
        for (int k = 0; k < 32; k++) {
            float a[8];
#pragma unroll
            for (int i = 0; i < 8; i++) a[i] = As[ty * 8 + i][k];
            const float4 b0 = *(const float4*)&Bs[k][tx * 4];
            const float4 b1 = *(const float4*)&Bs[k][64 + tx * 4];
            const float bv[8] = {b0.x, b0.y, b0.z, b0.w, b1.x, b1.y, b1.z, b1.w};
#pragma unroll
            for (int i = 0; i < 8; i++)
#pragma unroll
                for (int j = 0; j < 8; j++) acc[i][j] += a[i] * bv[j];
        }
        __syncthreads();
    }

    // epilogue: sigmoid(5x), coalesced float4 stores
#pragma unroll
    for (int i = 0; i < 8; i++) {
        const size_t row = (size_t)(m0 + ty * 8 + i);
        float4 o0, o1;
        o0.x = 1.0f / (1.0f + __expf(-5.0f * acc[i][0]));
        o0.y = 1.0f / (1.0f + __expf(-5.0f * acc[i][1]));
        o0.z = 1.0f / (1.0f + __expf(-5.0f * acc[i][2]));
        o0.w = 1.0f / (1.0f + __expf(-5.0f * acc[i][3]));
        o1.x = 1.0f / (1.0f + __expf(-5.0f * acc[i][4]));
        o1.y = 1.0f / (1.0f + __expf(-5.0f * acc[i][5]));
        o1.z = 1.0f / (1.0f + __expf(-5.0f * acc[i][6]));
        o1.w = 1.0f / (1.0f + __expf(-5.0f * acc[i][7]));
        *(float4*)(out + row * NHALF + n0 + tx * 4)      = o0;
        *(float4*)(out + row * NHALF + n0 + 64 + tx * 4) = o1;
    }
}

// ============================================================================
// kernel_launch: resolve inputs by element count, with positional fallback
// (metadata order: feat1, feat2, W1, b1, W2, b2, W3, b3).
// ============================================================================
extern "C" void kernel_launch(void* const* d_in, const int* in_sizes, int n_in,
                              void* d_out, int out_size)
{
    const float *f1 = nullptr, *f2 = nullptr;
    const float *W1 = nullptr, *b1 = nullptr, *W2 = nullptr, *b2 = nullptr;
    const float *W3 = nullptr, *b3 = nullptr;

    for (int i = 0; i < n_in; i++) {
        const float* p = (const float*)d_in[i];
        switch (in_sizes[i]) {
            case NHALF * NZ: if (!f1) f1 = p; else f2 = p; break;  // 16777216
            case NZ * D1:    W1 = p; break;                        // 524288
            case D1:         b1 = p; break;                        // 256
            case D1 * D2:    W2 = p; break;                        // 32768
            case D2:         b2 = p; break;                        // 128
            case D2 * D3:    W3 = p; break;                        // 8192
            case D3:         b3 = p; break;                        // 64
            default: break;
        }
    }
    // Positional fallback if size-based resolution failed (defensive).
    if (!f1 || !f2 || !W1 || !b1 || !W2 || !b2 || !W3 || !b3) {
        if (n_in >= 8) {
            f1 = (const float*)d_in[0]; f2 = (const float*)d_in[1];
            W1 = (const float*)d_in[2]; b1 = (const float*)d_in[3];
            W2 = (const float*)d_in[4]; b2 = (const float*)d_in[5];
            W3 = (const float*)d_in[6]; b3 = (const float*)d_in[7];
        } else {
            return;  // cannot resolve; avoid crashing the capture
        }
    }
    float* out = (float*)d_out;

    k1_gemm_relu<<<dim3(NROWS / 128, D1 / 64), 256>>>(f1, f2, W1, b1);
    k2_fused_tail<<<NROWS / 32, 256>>>(W2, b2, W3, b3);
    k3_cos_sigmoid<<<dim3(NHALF / 128, NHALF / 128), 256>>>(out);
}

// round 3
// speedup vs baseline: 1.6107x; 1.6107x over previous
#include <cuda_runtime.h>
#include <cstdint>

// ----------------------------------------------------------------------------
// Associative3DEmbedding: two-tower MLP (2048->256->128->64), normalize,
// all-pairs cosine -> sigmoid(5*cos).
//
// Round 3: k1 and k3 moved to tensor cores (mma.sync bf16) with split-bf16
// 3-term compensation (hi/lo): D = Ah*Bh + Al*Bh + Ah*Bl  (fp32 accum).
// Expected precision ~1e-5 rel (threshold 1e-3). k2 unchanged (fp32).
// ----------------------------------------------------------------------------

#define NZ    2048
#define D1    256
#define D2    128
#define D3    64
#define NHALF 8192
#define NROWS 16384

__device__ float g_h1[(size_t)NROWS * D1];  // 16 MB
__device__ float g_n [(size_t)NROWS * D3];  //  4 MB

// ---------------- bf16 split + mma helpers ----------------------------------

// round-to-nearest-even fp32 -> bf16 (upper 16 bits), manual (no header dep)
__device__ __forceinline__ uint32_t f2bf(float x) {
    uint32_t b = __float_as_uint(x);
    return (b + 0x7FFFu + ((b >> 16) & 1u)) >> 16;
}

// split two floats into packed-bf16 hi pair and lo pair (residual)
__device__ __forceinline__ void split_pair(float x0, float x1,
                                           uint32_t& hi, uint32_t& lo) {
    const uint32_t h0 = f2bf(x0);
    const uint32_t h1 = f2bf(x1);
    const float r0 = x0 - __uint_as_float(h0 << 16);
    const float r1 = x1 - __uint_as_float(h1 << 16);
    const uint32_t l0 = f2bf(r0);
    const uint32_t l1 = f2bf(r1);
    hi = h0 | (h1 << 16);
    lo = l0 | (l1 << 16);
}

__device__ __forceinline__ uint32_t smem_u32(const void* p) {
    return (uint32_t)__cvta_generic_to_shared(p);
}

__device__ __forceinline__ void ldsm_x4(uint32_t* r, uint32_t addr) {
    asm volatile("ldmatrix.sync.aligned.m8n8.x4.shared.b16 {%0,%1,%2,%3}, [%4];"
                 : "=r"(r[0]), "=r"(r[1]), "=r"(r[2]), "=r"(r[3]) : "r"(addr));
}
__device__ __forceinline__ void ldsm_x2(uint32_t* r, uint32_t addr) {
    asm volatile("ldmatrix.sync.aligned.m8n8.x2.shared.b16 {%0,%1}, [%2];"
                 : "=r"(r[0]), "=r"(r[1]) : "r"(addr));
}
__device__ __forceinline__ void ldsm_x2t(uint32_t* r, uint32_t addr) {
    asm volatile("ldmatrix.sync.aligned.m8n8.x2.trans.shared.b16 {%0,%1}, [%2];"
                 : "=r"(r[0]), "=r"(r[1]) : "r"(addr));
}
__device__ __forceinline__ void mma_bf16(float* d, const uint32_t* a,
                                         const uint32_t* b) {
    asm volatile(
        "mma.sync.aligned.m16n8k16.row.col.f32.bf16.bf16.f32 "
        "{%0,%1,%2,%3}, {%4,%5,%6,%7}, {%8,%9}, {%0,%1,%2,%3};"
        : "+f"(d[0]), "+f"(d[1]), "+f"(d[2]), "+f"(d[3])
        : "r"(a[0]), "r"(a[1]), "r"(a[2]), "r"(a[3]), "r"(b[0]), "r"(b[1]));
}

// ============================================================================
// k1: H1[16384,256] = relu(X @ W1 + b1) via split-bf16 tensor MMA.
// Block tile 128x128 (grid 128 x 2), 256 thr, 8 warps (2m x 4n), warp 64x32.
// K chunk 32, single-buffered smem, register prefetch of next chunk.
// smem strides padded for conflict-free ldmatrix: A row 40 bf16, B row 136.
// ============================================================================
#define K1_SA 40
#define K1_SB 136

__global__ __launch_bounds__(256) void k1_gemm_relu(
    const float* __restrict__ f1, const float* __restrict__ f2,
    const float* __restrict__ W1, const float* __restrict__ b1)
{
    __shared__ __align__(16) uint16_t sAh[128 * K1_SA], sAl[128 * K1_SA];
    __shared__ __align__(16) uint16_t sBh[32 * K1_SB],  sBl[32 * K1_SB];

    const int tid  = threadIdx.x;
    const int lane = tid & 31;
    const int wid  = tid >> 5;
    const int wm   = (wid >> 2) * 64;   // warp m offset (0,64)
    const int wn   = (wid & 3) * 32;    // warp n offset (0..96)
    const int row0 = blockIdx.x * 128;
    const int n0   = blockIdx.y * 128;

    const float* X = (row0 < NHALF) ? (f1 + (size_t)row0 * NZ)
                                    : (f2 + (size_t)(row0 - NHALF) * NZ);

    // per-thread load maps (K chunk = 32)
    // A: 128 rows x 8 f4  = 1024 f4, 4 per thread
    // B:  32 rows x 32 f4 = 1024 f4, 4 per thread (row = k, 128 n floats)
    int ar[4], ac[4], br[4], bc[4];
#pragma unroll
    for (int i = 0; i < 4; i++) {
        const int fa = tid + i * 256;
        ar[i] = fa >> 3;          ac[i] = (fa & 7) << 2;
        br[i] = fa >> 5;          bc[i] = (fa & 31) << 2;
    }

    float4 pa[4], pb[4];
#pragma unroll
    for (int i = 0; i < 4; i++) {
        pa[i] = *(const float4*)(X + (size_t)ar[i] * NZ + ac[i]);
        pb[i] = *(const float4*)(W1 + (size_t)br[i] * D1 + n0 + bc[i]);
    }

    float acc[4][4][4];
#pragma unroll
    for (int mi = 0; mi < 4; mi++)
#pragma unroll
        for (int ni = 0; ni < 4; ni++)
#pragma unroll
            for (int e = 0; e < 4; e++) acc[mi][ni][e] = 0.0f;

    const int NSTAGE = NZ / 32;  // 64
    for (int s = 0; s < NSTAGE; s++) {
        if (s) __syncthreads();
        // split + store current chunk
#pragma unroll
        for (int i = 0; i < 4; i++) {
            uint32_t h01, l01, h23, l23;
            split_pair(pa[i].x, pa[i].y, h01, l01);
            split_pair(pa[i].z, pa[i].w, h23, l23);
            const int o = ar[i] * K1_SA + ac[i];
            *(uint32_t*)(sAh + o)     = h01; *(uint32_t*)(sAh + o + 2) = h23;
            *(uint32_t*)(sAl + o)     = l01; *(uint32_t*)(sAl + o + 2) = l23;
            split_pair(pb[i].x, pb[i].y, h01, l01);
            split_pair(pb[i].z, pb[i].w, h23, l23);
            const int p = br[i] * K1_SB + bc[i];
            *(uint32_t*)(sBh + p)     = h01; *(uint32_t*)(sBh + p + 2) = h23;
            *(uint32_t*)(sBl + p)     = l01; *(uint32_t*)(sBl + p + 2) = l23;
        }
        __syncthreads();

        // prefetch next chunk
        if (s + 1 < NSTAGE) {
            const int kb = (s + 1) * 32;
#pragma unroll
            for (int i = 0; i < 4; i++) {
                pa[i] = *(const float4*)(X + (size_t)ar[i] * NZ + kb + ac[i]);
                pb[i] = *(const float4*)(W1 + (size_t)(kb + br[i]) * D1 + n0 + bc[i]);
            }
        }

        // MMA over the 32-wide chunk (two k16 steps, 3 split terms)
#pragma unroll
        for (int ks = 0; ks < 32; ks += 16) {
            uint32_t a_hi[4][4], a_lo[4][4], b_hi[4][2], b_lo[4][2];
            const int arow = (lane & 15);
            const int acol = ks + ((lane >> 4) << 3);
#pragma unroll
            for (int mi = 0; mi < 4; mi++) {
                const int off = (wm + mi * 16 + arow) * K1_SA + acol;
                ldsm_x4(a_hi[mi], smem_u32(sAh + off));
                ldsm_x4(a_lo[mi], smem_u32(sAl + off));
            }
            const int brow = ks + (lane & 15);
#pragma unroll
            for (int ni = 0; ni < 4; ni++) {
                const int off = brow * K1_SB + wn + ni * 8;
                ldsm_x2t(b_hi[ni], smem_u32(sBh + off));
                ldsm_x2t(b_lo[ni], smem_u32(sBl + off));
            }
#pragma unroll
            for (int mi = 0; mi < 4; mi++)
#pragma unroll
                for (int ni = 0; ni < 4; ni++) {
                    mma_bf16(acc[mi][ni], a_hi[mi], b_hi[ni]);
                    mma_bf16(acc[mi][ni], a_lo[mi], b_hi[ni]);
                    mma_bf16(acc[mi][ni], a_hi[mi], b_lo[ni]);
                }
        }
    }

    // epilogue: +bias, relu, store fp32 to g_h1
#pragma unroll
    for (int ni = 0; ni < 4; ni++) {
        const int col = n0 + wn + ni * 8 + ((lane & 3) << 1);
        const float bx = b1[col], by = b1[col + 1];
#pragma unroll
        for (int mi = 0; mi < 4; mi++) {
            const int r0 = row0 + wm + mi * 16 + (lane >> 2);
            float2 v0, v1;
            v0.x = fmaxf(acc[mi][ni][0] + bx, 0.0f);
            v0.y = fmaxf(acc[mi][ni][1] + by, 0.0f);
            v1.x = fmaxf(acc[mi][ni][2] + bx, 0.0f);
            v1.y = fmaxf(acc[mi][ni][3] + by, 0.0f);
            *(float2*)&g_h1[(size_t)r0 * D1 + col]       = v0;
            *(float2*)&g_h1[(size_t)(r0 + 8) * D1 + col] = v1;
        }
    }
}

// ============================================================================
// k2: fused  H2 = relu(H1@W2+b2); E = H2@W3+b3; N = E/max(||E||,1e-8)  (fp32)
// ============================================================================
__global__ __launch_bounds__(256) void k2_fused_tail(
    const float* __restrict__ W2, const float* __restrict__ b2,
    const float* __restrict__ W3, const float* __restrict__ b3)
{
    __shared__ float sm[32 * 256 + 32 * 128];
    float* sH1 = sm;
    float* sH2 = sm + 32 * 256;
    float* sE  = sm;
    float* sNrm = sm + 32 * 256;

    const int tid = threadIdx.x;
    const int r0  = blockIdx.x * 32;
    const float* src = g_h1 + (size_t)r0 * D1;

#pragma unroll
    for (int j = 0; j < 8; j++) {
        const int idx = tid + j * 256;
        *(float4*)&sH1[idx * 4] = *(const float4*)(src + (size_t)idx * 4);
    }
    __syncthreads();

    {
        const int jc = tid & 127;
        const int rh = tid >> 7;
        float acc[16];
#pragma unroll
        for (int r = 0; r < 16; r++) acc[r] = 0.0f;
        for (int k = 0; k < D1; k += 4) {
            const float w0 = W2[(size_t)(k + 0) * D2 + jc];
            const float w1 = W2[(size_t)(k + 1) * D2 + jc];
            const float w2 = W2[(size_t)(k + 2) * D2 + jc];
            const float w3 = W2[(size_t)(k + 3) * D2 + jc];
#pragma unroll
            for (int r = 0; r < 16; r++) {
                const float4 h = *(const float4*)&sH1[(rh * 16 + r) * D1 + k];
                acc[r] += h.x * w0 + h.y * w1 + h.z * w2 + h.w * w3;
            }
        }
        const float bb = b2[jc];
#pragma unroll
        for (int r = 0; r < 16; r++)
            sH2[(rh * 16 + r) * D2 + jc] = fmaxf(acc[r] + bb, 0.0f);
    }
    __syncthreads();

    {
        const int c  = tid & 63;
        const int rg = tid >> 6;
        float acc[8];
#pragma unroll
        for (int r = 0; r < 8; r++) acc[r] = 0.0f;
        for (int k = 0; k < D2; k += 4) {
            const float w0 = W3[(size_t)(k + 0) * D3 + c];
            const float w1 = W3[(size_t)(k + 1) * D3 + c];
            const float w2 = W3[(size_t)(k + 2) * D3 + c];
            const float w3 = W3[(size_t)(k + 3) * D3 + c];
#pragma unroll
            for (int r = 0; r < 8; r++) {
                const float4 h = *(const float4*)&sH2[(rg * 8 + r) * D2 + k];
                acc[r] += h.x * w0 + h.y * w1 + h.z * w2 + h.w * w3;
            }
        }
        const float bb = b3[c];
#pragma unroll
        for (int r = 0; r < 8; r++)
            sE[(rg * 8 + r) * D3 + c] = acc[r] + bb;
    }
    __syncthreads();

    if (tid < 32) {
        float ss = 0.0f;
#pragma unroll
        for (int c = 0; c < D3; c += 4) {
            const float4 e = *(const float4*)&sE[tid * D3 + c];
            ss += e.x * e.x + e.y * e.y + e.z * e.z + e.w * e.w;
        }
        sNrm[tid] = 1.0f / fmaxf(sqrtf(ss), 1e-8f);
    }
    __syncthreads();

    float* dst = g_n + (size_t)r0 * D3;
#pragma unroll
    for (int j = 0; j < 2; j++) {
        const int idx = tid + j * 256;
        const int r   = idx >> 4;
        const int c4  = (idx & 15) * 4;
        const float inv = sNrm[r];
        float4 e = *(const float4*)&sE[r * D3 + c4];
        e.x *= inv; e.y *= inv; e.z *= inv; e.w *= inv;
        *(float4*)(dst + (size_t)r * D3 + c4) = e;
    }
}

// ============================================================================
// k3: out = sigmoid(5 * N1 @ N2^T), K=64, split-bf16 tensor MMA.
// Block tile 128x128 (grid 64x64), 256 thr, 8 warps (2m x 4n), warp 64x32.
// Two K chunks of 32. A smem [m][k] (ldmatrix x4), B smem [n][k]
// (ldmatrix x2 NON-trans == .col B fragment). Strides padded to 40 bf16.
// ============================================================================
#define K3_S 40

__global__ __launch_bounds__(256) void k3_cos_sigmoid(float* __restrict__ out)
{
    __shared__ __align__(16) uint16_t sAh[128 * K3_S], sAl[128 * K3_S];
    __shared__ __align__(16) uint16_t sBh[128 * K3_S], sBl[128 * K3_S];

    const int tid  = threadIdx.x;
    const int lane = tid & 31;
    const int wid  = tid >> 5;
    const int wm   = (wid >> 2) * 64;
    const int wn   = (wid & 3) * 32;
    const int n0   = blockIdx.x * 128;
    const int m0   = blockIdx.y * 128;

    const float* Am = g_n + (size_t)m0 * D3;
    const float* Bm = g_n + (size_t)(NHALF + n0) * D3;

    float acc[4][4][4];
#pragma unroll
    for (int mi = 0; mi < 4; mi++)
#pragma unroll
        for (int ni = 0; ni < 4; ni++)
#pragma unroll
            for (int e = 0; e < 4; e++) acc[mi][ni][e] = 0.0f;

    // per-thread load map: 128 rows x 8 f4 = 1024 f4, 4 per thread
    int rr[4], cc[4];
#pragma unroll
    for (int i = 0; i < 4; i++) {
        const int f = tid + i * 256;
        rr[i] = f >> 3; cc[i] = (f & 7) << 2;
    }

    for (int kb = 0; kb < D3; kb += 32) {
        if (kb) __syncthreads();
#pragma unroll
        for (int i = 0; i < 4; i++) {
            const float4 va = *(const float4*)(Am + (size_t)rr[i] * D3 + kb + cc[i]);
            const float4 vb = *(const float4*)(Bm + (size_t)rr[i] * D3 + kb + cc[i]);
            uint32_t h01, l01, h23, l23;
            const int o = rr[i] * K3_S + cc[i];
            split_pair(va.x, va.y, h01, l01);
            split_pair(va.z, va.w, h23, l23);
            *(uint32_t*)(sAh + o) = h01; *(uint32_t*)(sAh + o + 2) = h23;
            *(uint32_t*)(sAl + o) = l01; *(uint32_t*)(sAl + o + 2) = l23;
            split_pair(vb.x, vb.y, h01, l01);
            split_pair(vb.z, vb.w, h23, l23);
            *(uint32_t*)(sBh + o) = h01; *(uint32_t*)(sBh + o + 2) = h23;
            *(uint32_t*)(sBl + o) = l01; *(uint32_t*)(sBl + o + 2) = l23;
        }
        __syncthreads();

#pragma unroll
        for (int ks = 0; ks < 32; ks += 16) {
            uint32_t a_hi[4][4], a_lo[4][4], b_hi[4][2], b_lo[4][2];
            const int arow = (lane & 15);
            const int acol = ks + ((lane >> 4) << 3);
#pragma unroll
            for (int mi = 0; mi < 4; mi++) {
                const int off = (wm + mi * 16 + arow) * K3_S + acol;
                ldsm_x4(a_hi[mi], smem_u32(sAh + off));
                ldsm_x4(a_lo[mi], smem_u32(sAl + off));
            }
            const int bn = (lane & 7);
            const int bk = ks + (((lane >> 3) & 1) << 3);
#pragma unroll
            for (int ni = 0; ni < 4; ni++) {
                const int off = (wn + ni * 8 + bn) * K3_S + bk;
                ldsm_x2(b_hi[ni], smem_u32(sBh + off));
                ldsm_x2(b_lo[ni], smem_u32(sBl + off));
            }
#pragma unroll
            for (int mi = 0; mi < 4; mi++)
#pragma unroll
                for (int ni = 0; ni < 4; ni++) {
                    mma_bf16(acc[mi][ni], a_hi[mi], b_hi[ni]);
                    mma_bf16(acc[mi][ni], a_lo[mi], b_hi[ni]);
                    mma_bf16(acc[mi][ni], a_hi[mi], b_lo[ni]);
                }
        }
    }

    // epilogue: sigmoid(5x), float2 stores (8B-aligned, full sectors)
#pragma unroll
    for (int mi = 0; mi < 4; mi++) {
        const int r0 = m0 + wm + mi * 16 + (lane >> 2);
#pragma unroll
        for (int ni = 0; ni < 4; ni++) {
            const int col = n0 + wn + ni * 8 + ((lane & 3) << 1);
            float2 v0, v1;
            v0.x = 1.0f / (1.0f + __expf(-5.0f * acc[mi][ni][0]));
            v0.y = 1.0f / (1.0f + __expf(-5.0f * acc[mi][ni][1]));
            v1.x = 1.0f / (1.0f + __expf(-5.0f * acc[mi][ni][2]));
            v1.y = 1.0f / (1.0f + __expf(-5.0f * acc[mi][ni][3]));
            *(float2*)(out + (size_t)r0 * NHALF + col)       = v0;
            *(float2*)(out + (size_t)(r0 + 8) * NHALF + col) = v1;
        }
    }
}

// ============================================================================
extern "C" void kernel_launch(void* const* d_in, const int* in_sizes, int n_in,
                              void* d_out, int out_size)
{
    const float *f1 = nullptr, *f2 = nullptr;
    const float *W1 = nullptr, *b1 = nullptr, *W2 = nullptr, *b2 = nullptr;
    const float *W3 = nullptr, *b3 = nullptr;

    for (int i = 0; i < n_in; i++) {
        const float* p = (const float*)d_in[i];
        switch (in_sizes[i]) {
            case NHALF * NZ: if (!f1) f1 = p; else f2 = p; break;
            case NZ * D1:    W1 = p; break;
            case D1:         b1 = p; break;
            case D1 * D2:    W2 = p; break;
            case D2:         b2 = p; break;
            case D2 * D3:    W3 = p; break;
            case D3:         b3 = p; break;
            default: break;
        }
    }
    if (!f1 || !f2 || !W1 || !b1 || !W2 || !b2 || !W3 || !b3) {
        if (n_in >= 8) {
            f1 = (const float*)d_in[0]; f2 = (const float*)d_in[1];
            W1 = (const float*)d_in[2]; b1 = (const float*)d_in[3];
            W2 = (const float*)d_in[4]; b2 = (const float*)d_in[5];
            W3 = (const float*)d_in[6]; b3 = (const float*)d_in[7];
        } else {
            return;
        }
    }
    float* out = (float*)d_out;

    k1_gemm_relu<<<dim3(NROWS / 128, D1 / 128), 256>>>(f1, f2, W1, b1);
    k2_fused_tail<<<NROWS / 32, 256>>>(W2, b2, W3, b3);
    k3_cos_sigmoid<<<dim3(NHALF / 128, NHALF / 128), 256>>>(out);
}

// round 4
// speedup vs baseline: 1.7205x; 1.0682x over previous
#include <cuda_runtime.h>
#include <cstdint>

// ----------------------------------------------------------------------------
// Associative3DEmbedding — Round 4.
// R3 post-mortem: k1 alu=31.6% (in-loop fp32->bf16 split) strangled tensor
// pipe (39.3%), occ 12.5%. Fix: pre-split X/W1 to gmem bf16 hi/lo (k0),
// k2 writes pre-split normalized embeddings, so k1/k3 hot loops are pure
// cp.async + ldmatrix + 3-term bf16 MMA.
// ----------------------------------------------------------------------------

#define NZ    2048
#define D1    256
#define D2    128
#define D3    64
#define NHALF 8192
#define NROWS 16384

__device__ float    g_h1 [(size_t)NROWS * D1];   // 16 MB
__device__ uint16_t g_xh [(size_t)NROWS * NZ];   // 64 MB  X hi
__device__ uint16_t g_xl [(size_t)NROWS * NZ];   // 64 MB  X lo
__device__ uint16_t g_w1h[(size_t)NZ * D1];      //  1 MB
__device__ uint16_t g_w1l[(size_t)NZ * D1];      //  1 MB
__device__ uint16_t g_nh [(size_t)NROWS * D3];   //  2 MB  normalized hi
__device__ uint16_t g_nl [(size_t)NROWS * D3];   //  2 MB  normalized lo

// ---------------- helpers ----------------------------------------------------

__device__ __forceinline__ uint32_t f2bf(float x) {
    uint32_t b = __float_as_uint(x);
    return (b + 0x7FFFu + ((b >> 16) & 1u)) >> 16;
}
__device__ __forceinline__ void split_pair(float x0, float x1,
                                           uint32_t& hi, uint32_t& lo) {
    const uint32_t h0 = f2bf(x0);
    const uint32_t h1 = f2bf(x1);
    const float r0 = x0 - __uint_as_float(h0 << 16);
    const float r1 = x1 - __uint_as_float(h1 << 16);
    hi = h0 | (h1 << 16);
    lo = f2bf(r0) | (f2bf(r1) << 16);
}
__device__ __forceinline__ uint32_t smem_u32(const void* p) {
    return (uint32_t)__cvta_generic_to_shared(p);
}
__device__ __forceinline__ void cp16(uint32_t saddr, const void* g) {
    asm volatile("cp.async.cg.shared.global [%0], [%1], 16;"
                 :: "r"(saddr), "l"(g));
}
__device__ __forceinline__ void cp_commit() {
    asm volatile("cp.async.commit_group;");
}
template <int N>
__device__ __forceinline__ void cp_wait() {
    asm volatile("cp.async.wait_group %0;" :: "n"(N));
}
__device__ __forceinline__ void ldsm_x4(uint32_t* r, uint32_t addr) {
    asm volatile("ldmatrix.sync.aligned.m8n8.x4.shared.b16 {%0,%1,%2,%3}, [%4];"
                 : "=r"(r[0]), "=r"(r[1]), "=r"(r[2]), "=r"(r[3]) : "r"(addr));
}
__device__ __forceinline__ void ldsm_x2(uint32_t* r, uint32_t addr) {
    asm volatile("ldmatrix.sync.aligned.m8n8.x2.shared.b16 {%0,%1}, [%2];"
                 : "=r"(r[0]), "=r"(r[1]) : "r"(addr));
}
__device__ __forceinline__ void ldsm_x2t(uint32_t* r, uint32_t addr) {
    asm volatile("ldmatrix.sync.aligned.m8n8.x2.trans.shared.b16 {%0,%1}, [%2];"
                 : "=r"(r[0]), "=r"(r[1]) : "r"(addr));
}
__device__ __forceinline__ void mma_bf16(float* d, const uint32_t* a,
                                         const uint32_t* b) {
    asm volatile(
        "mma.sync.aligned.m16n8k16.row.col.f32.bf16.bf16.f32 "
        "{%0,%1,%2,%3}, {%4,%5,%6,%7}, {%8,%9}, {%0,%1,%2,%3};"
        : "+f"(d[0]), "+f"(d[1]), "+f"(d[2]), "+f"(d[3])
        : "r"(a[0]), "r"(a[1]), "r"(a[2]), "r"(a[3]), "r"(b[0]), "r"(b[1]));
}

// ============================================================================
// k0a: split X=[feat1;feat2] into g_xh/g_xl.  k0b: split W1 into g_w1h/g_w1l.
// Pure streaming: float4 in -> uint2 hi + uint2 lo out.
// ============================================================================
__global__ __launch_bounds__(256) void k0_split_x(
    const float* __restrict__ f1, const float* __restrict__ f2)
{
    const size_t total4 = (size_t)NROWS * NZ / 4;
    const size_t half4  = (size_t)NHALF * NZ / 4;
    uint2* oh = (uint2*)g_xh;
    uint2* ol = (uint2*)g_xl;
    for (size_t i = blockIdx.x * 256ull + threadIdx.x; i < total4;
         i += (size_t)gridDim.x * 256ull) {
        const float4 v = (i < half4)
            ? *(const float4*)(f1 + i * 4)
            : *(const float4*)(f2 + (i - half4) * 4);
        uint32_t h01, l01, h23, l23;
        split_pair(v.x, v.y, h01, l01);
        split_pair(v.z, v.w, h23, l23);
        oh[i] = make_uint2(h01, h23);
        ol[i] = make_uint2(l01, l23);
    }
}

__global__ __launch_bounds__(256) void k0_split_w(const float* __restrict__ W1)
{
    const size_t total4 = (size_t)NZ * D1 / 4;
    uint2* oh = (uint2*)g_w1h;
    uint2* ol = (uint2*)g_w1l;
    for (size_t i = blockIdx.x * 256ull + threadIdx.x; i < total4;
         i += (size_t)gridDim.x * 256ull) {
        const float4 v = *(const float4*)(W1 + i * 4);
        uint32_t h01, l01, h23, l23;
        split_pair(v.x, v.y, h01, l01);
        split_pair(v.z, v.w, h23, l23);
        oh[i] = make_uint2(h01, h23);
        ol[i] = make_uint2(l01, l23);
    }
}

// ============================================================================
// k1: H1[16384,256] = relu(X @ W1 + b1), pure bf16 3-term MMA.
// BM=64, BN=256 (full D1; X read once), BK=32, grid=256, 256 thr, 8 warps
// (2m x 4n), warp tile 32x64. cp.async double-buffered. Dynamic smem 86KB.
// A stride 40 u16 (conflict-free ldmatrix), B stride 264 u16.
// ============================================================================
#define K1_SA 40
#define K1_SB 264
#define K1_A_BUF (64 * K1_SA)          // u16 per A buffer
#define K1_B_BUF (32 * K1_SB)          // u16 per B buffer
// layout (u16 offsets): AH[2], AL[2], BH[2], BL[2]
#define K1_AH 0
#define K1_AL (2 * K1_A_BUF)
#define K1_BH (4 * K1_A_BUF)
#define K1_BL (4 * K1_A_BUF + 2 * K1_B_BUF)
#define K1_SMEM_BYTES ((4 * K1_A_BUF + 4 * K1_B_BUF) * 2)

__global__ __launch_bounds__(256, 2) void k1_gemm_relu(
    const float* __restrict__ b1)
{
    extern __shared__ uint16_t dsm[];

    const int tid  = threadIdx.x;
    const int lane = tid & 31;
    const int wid  = tid >> 5;
    const int wm   = (wid >> 2) * 32;    // 0,32
    const int wn   = (wid & 3) * 64;     // 0..192
    const int row0 = blockIdx.x * 64;

    // load maps
    const int a_row = tid >> 2;          // 0..63
    const int a_kc  = (tid & 3) * 8;     // u16 offset within 32-k row
    const int b_row = tid >> 5;          // 0..7 (+8 per i)
    const int b_nc  = (tid & 31) * 8;

    const uint16_t* gA_h = g_xh + (size_t)(row0 + a_row) * NZ + a_kc;
    const uint16_t* gA_l = g_xl + (size_t)(row0 + a_row) * NZ + a_kc;

    auto load_stage = [&](int s, int buf) {
        const int kb = s * 32;
        const uint32_t sa = smem_u32(dsm) + (uint32_t)(a_row * K1_SA + a_kc) * 2;
        cp16(sa + (K1_AH + buf * K1_A_BUF) * 2, gA_h + kb);
        cp16(sa + (K1_AL + buf * K1_A_BUF) * 2, gA_l + kb);
#pragma unroll
        for (int i = 0; i < 4; i++) {
            const int kr = b_row + i * 8;
            const uint32_t sb = smem_u32(dsm) +
                (uint32_t)(kr * K1_SB + b_nc) * 2;
            const size_t go = (size_t)(kb + kr) * D1 + b_nc;
            cp16(sb + (K1_BH + buf * K1_B_BUF) * 2, g_w1h + go);
            cp16(sb + (K1_BL + buf * K1_B_BUF) * 2, g_w1l + go);
        }
        cp_commit();
    };

    float acc[2][8][4];
#pragma unroll
    for (int mi = 0; mi < 2; mi++)
#pragma unroll
        for (int ni = 0; ni < 8; ni++)
#pragma unroll
            for (int e = 0; e < 4; e++) acc[mi][ni][e] = 0.0f;

    load_stage(0, 0);

    const int NSTAGE = NZ / 32;  // 64
    int buf = 0;
    for (int s = 0; s < NSTAGE; s++) {
        cp_wait<0>();
        __syncthreads();
        if (s + 1 < NSTAGE) load_stage(s + 1, buf ^ 1);

        const uint16_t* Ah = dsm + K1_AH + buf * K1_A_BUF;
        const uint16_t* Al = dsm + K1_AL + buf * K1_A_BUF;
        const uint16_t* Bh = dsm + K1_BH + buf * K1_B_BUF;
        const uint16_t* Bl = dsm + K1_BL + buf * K1_B_BUF;

#pragma unroll
        for (int ks = 0; ks < 32; ks += 16) {
            uint32_t a_hi[2][4], a_lo[2][4];
            const int aoff = (lane & 15) * K1_SA + ks + ((lane >> 4) << 3);
#pragma unroll
            for (int mi = 0; mi < 2; mi++) {
                const int off = (wm + mi * 16) * K1_SA + aoff;
                ldsm_x4(a_hi[mi], smem_u32(Ah + off));
                ldsm_x4(a_lo[mi], smem_u32(Al + off));
            }
            const int boff = (ks + (lane & 15)) * K1_SB + wn;
#pragma unroll
            for (int g = 0; g < 2; g++) {
                uint32_t b_hi[4][2], b_lo[4][2];
#pragma unroll
                for (int nj = 0; nj < 4; nj++) {
                    const int off = boff + (g * 4 + nj) * 8;
                    ldsm_x2t(b_hi[nj], smem_u32(Bh + off));
                    ldsm_x2t(b_lo[nj], smem_u32(Bl + off));
                }
#pragma unroll
                for (int mi = 0; mi < 2; mi++)
#pragma unroll
                    for (int nj = 0; nj < 4; nj++) {
                        float* d = acc[mi][g * 4 + nj];
                        mma_bf16(d, a_hi[mi], b_hi[nj]);
                        mma_bf16(d, a_lo[mi], b_hi[nj]);
                        mma_bf16(d, a_hi[mi], b_lo[nj]);
                    }
            }
        }
        __syncthreads();
        buf ^= 1;
    }

    // epilogue: +bias, relu, store fp32
#pragma unroll
    for (int ni = 0; ni < 8; ni++) {
        const int col = wn + ni * 8 + ((lane & 3) << 1);
        const float bx = b1[col], by = b1[col + 1];
#pragma unroll
        for (int mi = 0; mi < 2; mi++) {
            const int r = row0 + wm + mi * 16 + (lane >> 2);
            float2 v0, v1;
            v0.x = fmaxf(acc[mi][ni][0] + bx, 0.0f);
            v0.y = fmaxf(acc[mi][ni][1] + by, 0.0f);
            v1.x = fmaxf(acc[mi][ni][2] + bx, 0.0f);
            v1.y = fmaxf(acc[mi][ni][3] + by, 0.0f);
            *(float2*)&g_h1[(size_t)r * D1 + col]       = v0;
            *(float2*)&g_h1[(size_t)(r + 8) * D1 + col] = v1;
        }
    }
}

// ============================================================================
// k2: fused H2 = relu(H1@W2+b2); E = H2@W3+b3; N = E/max(||E||,1e-8).
// Epilogue now writes PRE-SPLIT bf16 hi/lo to g_nh/g_nl.
// ============================================================================
__global__ __launch_bounds__(256) void k2_fused_tail(
    const float* __restrict__ W2, const float* __restrict__ b2,
    const float* __restrict__ W3, const float* __restrict__ b3)
{
    __shared__ float sm[32 * 256 + 32 * 128];
    float* sH1 = sm;
    float* sH2 = sm + 32 * 256;
    float* sE  = sm;
    float* sNrm = sm + 32 * 256;

    const int tid = threadIdx.x;
    const int r0  = blockIdx.x * 32;
    const float* src = g_h1 + (size_t)r0 * D1;

#pragma unroll
    for (int j = 0; j < 8; j++) {
        const int idx = tid + j * 256;
        *(float4*)&sH1[idx * 4] = *(const float4*)(src + (size_t)idx * 4);
    }
    __syncthreads();

    {
        const int jc = tid & 127;
        const int rh = tid >> 7;
        float acc[16];
#pragma unroll
        for (int r = 0; r < 16; r++) acc[r] = 0.0f;
        for (int k = 0; k < D1; k += 4) {
            const float w0 = W2[(size_t)(k + 0) * D2 + jc];
            const float w1 = W2[(size_t)(k + 1) * D2 + jc];
            const float w2 = W2[(size_t)(k + 2) * D2 + jc];
            const float w3 = W2[(size_t)(k + 3) * D2 + jc];
#pragma unroll
            for (int r = 0; r < 16; r++) {
                const float4 h = *(const float4*)&sH1[(rh * 16 + r) * D1 + k];
                acc[r] += h.x * w0 + h.y * w1 + h.z * w2 + h.w * w3;
            }
        }
        const float bb = b2[jc];
#pragma unroll
        for (int r = 0; r < 16; r++)
            sH2[(rh * 16 + r) * D2 + jc] = fmaxf(acc[r] + bb, 0.0f);
    }
    __syncthreads();

    {
        const int c  = tid & 63;
        const int rg = tid >> 6;
        float acc[8];
#pragma unroll
        for (int r = 0; r < 8; r++) acc[r] = 0.0f;
        for (int k = 0; k < D2; k += 4) {
            const float w0 = W3[(size_t)(k + 0) * D3 + c];
            const float w1 = W3[(size_t)(k + 1) * D3 + c];
            const float w2 = W3[(size_t)(k + 2) * D3 + c];
            const float w3 = W3[(size_t)(k + 3) * D3 + c];
#pragma unroll
            for (int r = 0; r < 8; r++) {
                const float4 h = *(const float4*)&sH2[(rg * 8 + r) * D2 + k];
                acc[r] += h.x * w0 + h.y * w1 + h.z * w2 + h.w * w3;
            }
        }
        const float bb = b3[c];
#pragma unroll
        for (int r = 0; r < 8; r++)
            sE[(rg * 8 + r) * D3 + c] = acc[r] + bb;
    }
    __syncthreads();

    if (tid < 32) {
        float ss = 0.0f;
#pragma unroll
        for (int c = 0; c < D3; c += 4) {
            const float4 e = *(const float4*)&sE[tid * D3 + c];
            ss += e.x * e.x + e.y * e.y + e.z * e.z + e.w * e.w;
        }
        sNrm[tid] = 1.0f / fmaxf(sqrtf(ss), 1e-8f);
    }
    __syncthreads();

    // normalize + split-store to g_nh / g_nl
    uint2* oh = (uint2*)g_nh;
    uint2* ol = (uint2*)g_nl;
#pragma unroll
    for (int j = 0; j < 2; j++) {
        const int idx = tid + j * 256;          // f4 index, 512 total
        const int r   = idx >> 4;               // 16 f4 per row
        const int c4  = idx & 15;
        const float inv = sNrm[r];
        float4 e = *(const float4*)&sE[r * D3 + c4 * 4];
        e.x *= inv; e.y *= inv; e.z *= inv; e.w *= inv;
        uint32_t h01, l01, h23, l23;
        split_pair(e.x, e.y, h01, l01);
        split_pair(e.z, e.w, h23, l23);
        const size_t o = (size_t)(r0 + r) * (D3 / 4) + c4;
        oh[o] = make_uint2(h01, h23);
        ol[o] = make_uint2(l01, l23);
    }
}

// ============================================================================
// k3: out = sigmoid(5 * N1 @ N2^T), K=64 in ONE shot (no k staging).
// BM=BN=128, 256 thr, 8 warps (2m x 4n), warp 64x32. 16 cp.async / thread.
// A,B strides 72 u16 (144 B, conflict-free). Dynamic smem 72KB.
// ============================================================================
#define K3_S 72
#define K3_T (128 * K3_S)     // u16 per tile
#define K3_AH 0
#define K3_AL (1 * K3_T)
#define K3_BH (2 * K3_T)
#define K3_BL (3 * K3_T)
#define K3_SMEM_BYTES (4 * K3_T * 2)

__global__ __launch_bounds__(256, 2) void k3_cos_sigmoid(float* __restrict__ out)
{
    extern __shared__ uint16_t dsm[];

    const int tid  = threadIdx.x;
    const int lane = tid & 31;
    const int wid  = tid >> 5;
    const int wm   = (wid >> 2) * 64;
    const int wn   = (wid & 3) * 32;
    const int n0   = blockIdx.x * 128;
    const int m0   = blockIdx.y * 128;

    // load maps: 128 rows x 8 chunks(16B) per tile; 4 chunks per thread
#pragma unroll
    for (int i = 0; i < 4; i++) {
        const int c   = tid + i * 256;
        const int row = c >> 3;
        const int kc  = (c & 7) * 8;     // u16 offset
        const uint32_t so = smem_u32(dsm) + (uint32_t)(row * K3_S + kc) * 2;
        const size_t ga = (size_t)(m0 + row) * D3 + kc;
        const size_t gb = (size_t)(NHALF + n0 + row) * D3 + kc;
        cp16(so + K3_AH * 2, g_nh + ga);
        cp16(so + K3_AL * 2, g_nl + ga);
        cp16(so + K3_BH * 2, g_nh + gb);
        cp16(so + K3_BL * 2, g_nl + gb);
    }
    cp_commit();

    float acc[4][4][4];
#pragma unroll
    for (int mi = 0; mi < 4; mi++)
#pragma unroll
        for (int ni = 0; ni < 4; ni++)
#pragma unroll
            for (int e = 0; e < 4; e++) acc[mi][ni][e] = 0.0f;

    cp_wait<0>();
    __syncthreads();

    const uint16_t* Ah = dsm + K3_AH;
    const uint16_t* Al = dsm + K3_AL;
    const uint16_t* Bh = dsm + K3_BH;
    const uint16_t* Bl = dsm + K3_BL;

#pragma unroll
    for (int ks = 0; ks < 64; ks += 16) {
        uint32_t a_hi[4][4], a_lo[4][4];
        const int aoff = (lane & 15) * K3_S + ks + ((lane >> 4) << 3);
#pragma unroll
        for (int mi = 0; mi < 4; mi++) {
            const int off = (wm + mi * 16) * K3_S + aoff;
            ldsm_x4(a_hi[mi], smem_u32(Ah + off));
            ldsm_x4(a_lo[mi], smem_u32(Al + off));
        }
        const int boff = (lane & 7) * K3_S + ks + (((lane >> 3) & 1) << 3);
#pragma unroll
        for (int g = 0; g < 2; g++) {
            uint32_t b_hi[2][2], b_lo[2][2];
#pragma unroll
            for (int nj = 0; nj < 2; nj++) {
                const int off = (wn + (g * 2 + nj) * 8) * K3_S + boff;
                ldsm_x2(b_hi[nj], smem_u32(Bh + off));
                ldsm_x2(b_lo[nj], smem_u32(Bl + off));
            }
#pragma unroll
            for (int mi = 0; mi < 4; mi++)
#pragma unroll
                for (int nj = 0; nj < 2; nj++) {
                    float* d = acc[mi][g * 2 + nj];
                    mma_bf16(d, a_hi[mi], b_hi[nj]);
                    mma_bf16(d, a_lo[mi], b_hi[nj]);
                    mma_bf16(d, a_hi[mi], b_lo[nj]);
                }
        }
    }

    // epilogue: sigmoid(5x), float2 stores
#pragma unroll
    for (int mi = 0; mi < 4; mi++) {
        const int r = m0 + wm + mi * 16 + (lane >> 2);
#pragma unroll
        for (int ni = 0; ni < 4; ni++) {
            const int col = n0 + wn + ni * 8 + ((lane & 3) << 1);
            float2 v0, v1;
            v0.x = 1.0f / (1.0f + __expf(-5.0f * acc[mi][ni][0]));
            v0.y = 1.0f / (1.0f + __expf(-5.0f * acc[mi][ni][1]));
            v1.x = 1.0f / (1.0f + __expf(-5.0f * acc[mi][ni][2]));
            v1.y = 1.0f / (1.0f + __expf(-5.0f * acc[mi][ni][3]));
            *(float2*)(out + (size_t)r * NHALF + col)       = v0;
            *(float2*)(out + (size_t)(r + 8) * NHALF + col) = v1;
        }
    }
}

// ============================================================================
extern "C" void kernel_launch(void* const* d_in, const int* in_sizes, int n_in,
                              void* d_out, int out_size)
{
    const float *f1 = nullptr, *f2 = nullptr;
    const float *W1 = nullptr, *b1 = nullptr, *W2 = nullptr, *b2 = nullptr;
    const float *W3 = nullptr, *b3 = nullptr;

    for (int i = 0; i < n_in; i++) {
        const float* p = (const float*)d_in[i];
        switch (in_sizes[i]) {
            case NHALF * NZ: if (!f1) f1 = p; else f2 = p; break;
            case NZ * D1:    W1 = p; break;
            case D1:         b1 = p; break;
            case D1 * D2:    W2 = p; break;
            case D2:         b2 = p; break;
            case D2 * D3:    W3 = p; break;
            case D3:         b3 = p; break;
            default: break;
        }
    }
    if (!f1 || !f2 || !W1 || !b1 || !W2 || !b2 || !W3 || !b3) {
        if (n_in >= 8) {
            f1 = (const float*)d_in[0]; f2 = (const float*)d_in[1];
            W1 = (const float*)d_in[2]; b1 = (const float*)d_in[3];
            W2 = (const float*)d_in[4]; b2 = (const float*)d_in[5];
            W3 = (const float*)d_in[6]; b3 = (const float*)d_in[7];
        } else {
            return;
        }
    }
    float* out = (float*)d_out;

    // dynamic-smem opt-in (idempotent; host attribute call, capture-safe)
    static bool attr_done = false;
    if (!attr_done) {
        cudaFuncSetAttribute(k1_gemm_relu,
            cudaFuncAttributeMaxDynamicSharedMemorySize, K1_SMEM_BYTES);
        cudaFuncSetAttribute(k3_cos_sigmoid,
            cudaFuncAttributeMaxDynamicSharedMemorySize, K3_SMEM_BYTES);
        attr_done = true;
    }

    k0_split_x<<<2048, 256>>>(f1, f2);
    k0_split_w<<<512, 256>>>(W1);
    k1_gemm_relu<<<NROWS / 64, 256, K1_SMEM_BYTES>>>(b1);
    k2_fused_tail<<<NROWS / 32, 256>>>(W2, b2, W3, b3);
    k3_cos_sigmoid<<<dim3(NHALF / 128, NHALF / 128), 256, K3_SMEM_BYTES>>>(out);
}